// round 1
// baseline (speedup 1.0000x reference)
#include <cuda_runtime.h>
#include <cstdint>

// Problem constants
#define HB 200
#define WB 200
#define HW 40000          // H*W
#define BQ 4              // batch
#define NBT 8             // 2*batch (cat)
#define CI 128            // input channels
#define CE 64             // embed channels
#define RR 4              // neighborhood radius (NEI=9 -> R=4)
#define K81 81            // 9x9 offsets

typedef unsigned long long ull;

// ---------------- packed f32x2 helpers (Blackwell FFMA2 path) ----------------
__device__ __forceinline__ ull pack2(float x, float y) {
    ull r; asm("mov.b64 %0,{%1,%2};" : "=l"(r) : "f"(x), "f"(y)); return r;
}
__device__ __forceinline__ float2 unpack2(ull v) {
    float2 r; asm("mov.b64 {%0,%1},%2;" : "=f"(r.x), "=f"(r.y) : "l"(v)); return r;
}
__device__ __forceinline__ void ffma2(ull& c, ull a, ull b) {
    asm("fma.rn.f32x2 %0,%1,%2,%0;" : "+l"(c) : "l"(a), "l"(b));
}

// ---------------- scratch (device globals; no allocation allowed) ------------
__device__ float g_T1 [(size_t)NBT * CE * HW];   // ec1 out, NCHW [8][64][HW]
__device__ float g_E2 [(size_t)NBT * HW * CE];   // ec2 out, NHWC [8][HW][64]
__device__ float g_W81[(size_t)BQ  * HW * K81];  // softmax weights [4][HW][81]
__device__ float g_FSN[(size_t)BQ  * HW * CI];   // feature_select NHWC
__device__ float g_ALN[(size_t)BQ  * HW * CI];   // align NHWC
__device__ float g_ALC[(size_t)BQ  * CI * HW];   // align NCHW
__device__ float g_A1 [(size_t)NBT * CE * HW];   // ag1 out NCHW
__device__ float g_A2 [(size_t)NBT * 32 * HW];   // ag2 out NCHW
__device__ float g_A3 [(size_t)NBT * HW];        // ag3 out [8][HW]

// ---------------- generic 32x32 tiled transpose: [n][A][B] -> [n][B][A] ------
__global__ void k_trans(const float* __restrict__ src, float* __restrict__ dst,
                        int A, int B) {
    __shared__ float t[32][33];
    int n = blockIdx.z;
    size_t base = (size_t)n * A * B;
    int a0 = blockIdx.y * 32, b0 = blockIdx.x * 32;
    int tx = threadIdx.x, ty = threadIdx.y;
#pragma unroll
    for (int i = 0; i < 4; i++) {
        int a = a0 + ty + i * 8, b = b0 + tx;
        if (a < A && b < B) t[ty + i * 8][tx] = src[base + (size_t)a * B + b];
    }
    __syncthreads();
#pragma unroll
    for (int i = 0; i < 4; i++) {
        int b = b0 + ty + i * 8, a = a0 + tx;
        if (a < A && b < B) dst[base + (size_t)b * A + a] = t[tx][ty + i * 8];
    }
}

// ---------------- 1x1 conv + ReLU:  NCHW in -> NCHW out (OC=64) --------------
// block = 256 threads = 4 oc-groups x 64 pixel-lanes; 4 pixels per thread.
// Each thread computes 16 oc for 4 pixels; weights in shared (warp-broadcast).
template <int IC>
__global__ __launch_bounds__(256) void k_conv1(
    const float* __restrict__ in0,   // batches 0..3 base (NCHW [4][IC][HW])
    const float* __restrict__ in1,   // batches 4..7 base (NCHW [4][IC][HW])
    const float* __restrict__ w,     // [64][IC]
    const float* __restrict__ bias,  // [64]
    float* __restrict__ out)         // NCHW [8][64][HW]
{
    __shared__ __align__(16) float ws[IC][64];  // [ic][oc]
    int n = blockIdx.y;
    const float* src = ((n < BQ) ? in0 : in1) + (size_t)(n & 3) * IC * HW;
    int tid = threadIdx.x;
    for (int i = tid; i < IC * 64; i += 256) {
        int ic = i >> 6, oc = i & 63;
        ws[ic][oc] = w[oc * IC + ic];
    }
    __syncthreads();

    int ocg = tid >> 6, j = tid & 63;
    int pb = blockIdx.x * 256;
    int p[4]; bool pv[4];
#pragma unroll
    for (int m = 0; m < 4; m++) { p[m] = pb + j + 64 * m; pv[m] = p[m] < HW; }

    ull acc[4][8];
#pragma unroll
    for (int m = 0; m < 4; m++)
#pragma unroll
        for (int u = 0; u < 8; u++) acc[m][u] = 0ull;

    for (int ic = 0; ic < IC; ic++) {
        ull x2[4];
#pragma unroll
        for (int m = 0; m < 4; m++) {
            float xv = pv[m] ? src[(size_t)ic * HW + p[m]] : 0.f;
            x2[m] = pack2(xv, xv);
        }
        const ull* wr = reinterpret_cast<const ull*>(&ws[ic][ocg * 16]);
        ull wv[8];
#pragma unroll
        for (int u = 0; u < 8; u++) wv[u] = wr[u];
#pragma unroll
        for (int m = 0; m < 4; m++)
#pragma unroll
            for (int u = 0; u < 8; u++) ffma2(acc[m][u], wv[u], x2[m]);
    }

    float* op = out + (size_t)n * 64 * HW;
#pragma unroll
    for (int m = 0; m < 4; m++) {
        if (!pv[m]) continue;
#pragma unroll
        for (int u = 0; u < 8; u++) {
            float2 v = unpack2(acc[m][u]);
            int oc = ocg * 16 + 2 * u;
            op[(size_t)oc * HW + p[m]]       = fmaxf(v.x + bias[oc], 0.f);
            op[(size_t)(oc + 1) * HW + p[m]] = fmaxf(v.y + bias[oc + 1], 0.f);
        }
    }
}

// ---------------- 3x3 conv + ReLU: NCHW in (IC=64) -> NHWC or NCHW out -------
template <int OC, bool NHWC_OUT>
__global__ __launch_bounds__(256) void k_conv3(
    const float* __restrict__ in,    // NCHW [8][64][HW]
    const float* __restrict__ w,     // [OC][64][3][3]
    const float* __restrict__ bias,  // [OC]
    float* __restrict__ out)
{
    constexpr int OPT = OC / 4;   // oc per thread (16 or 8)
    constexpr int NU  = OPT / 2;  // f32x2 pairs per thread (8 or 4)
    __shared__ __align__(16) float ws[CE][OC];
    int n = blockIdx.y;
    const float* src = in + (size_t)n * CE * HW;
    int tid = threadIdx.x;
    int ocg = tid >> 6, j = tid & 63;
    int ocbase = ocg * OPT;
    int pb = blockIdx.x * 256;

    int p[4], y[4], x[4]; bool pv[4];
#pragma unroll
    for (int m = 0; m < 4; m++) {
        p[m] = pb + j + 64 * m;
        pv[m] = p[m] < HW;
        int pp = pv[m] ? p[m] : 0;
        y[m] = pp / WB; x[m] = pp - y[m] * WB;
    }

    ull acc[4][NU];
#pragma unroll
    for (int m = 0; m < 4; m++)
#pragma unroll
        for (int u = 0; u < NU; u++) acc[m][u] = 0ull;

    for (int tap = 0; tap < 9; tap++) {
        int dy = tap / 3 - 1, dx = tap % 3 - 1;
        __syncthreads();
        for (int i = tid; i < CE * OC; i += 256) {
            int ic = i / OC, oc = i - ic * OC;
            ws[ic][oc] = w[((size_t)oc * CE + ic) * 9 + tap];
        }
        __syncthreads();

        bool v[4]; int off[4];
#pragma unroll
        for (int m = 0; m < 4; m++) {
            v[m] = pv[m] && ((unsigned)(y[m] + dy) < HB) && ((unsigned)(x[m] + dx) < WB);
            off[m] = p[m] + dy * WB + dx;
        }
        for (int ic = 0; ic < CE; ic++) {
            ull x2[4];
#pragma unroll
            for (int m = 0; m < 4; m++) {
                float xv = v[m] ? src[(size_t)ic * HW + off[m]] : 0.f;
                x2[m] = pack2(xv, xv);
            }
            const ull* wr = reinterpret_cast<const ull*>(&ws[ic][ocbase]);
            ull wv[NU];
#pragma unroll
            for (int u = 0; u < NU; u++) wv[u] = wr[u];
#pragma unroll
            for (int m = 0; m < 4; m++)
#pragma unroll
                for (int u = 0; u < NU; u++) ffma2(acc[m][u], wv[u], x2[m]);
        }
    }

#pragma unroll
    for (int m = 0; m < 4; m++) {
        if (!pv[m]) continue;
        if (NHWC_OUT) {
            float* ob = out + ((size_t)n * HW + p[m]) * OC + ocbase;
#pragma unroll
            for (int u = 0; u < NU; u++) {
                float2 vv = unpack2(acc[m][u]);
                int oc = ocbase + 2 * u;
                ob[2 * u]     = fmaxf(vv.x + bias[oc], 0.f);
                ob[2 * u + 1] = fmaxf(vv.y + bias[oc + 1], 0.f);
            }
        } else {
            float* ob = out + (size_t)n * OC * HW;
#pragma unroll
            for (int u = 0; u < NU; u++) {
                float2 vv = unpack2(acc[m][u]);
                int oc = ocbase + 2 * u;
                ob[(size_t)oc * HW + p[m]]       = fmaxf(vv.x + bias[oc], 0.f);
                ob[(size_t)(oc + 1) * HW + p[m]] = fmaxf(vv.y + bias[oc + 1], 0.f);
            }
        }
    }
}

// ---------------- correlation (81 offsets) + softmax, fused ------------------
// warp per pixel; lanes over 64 embed channels as float2; shfl-reduce per k.
__global__ __launch_bounds__(256) void k_corr(
    const float* __restrict__ e2,   // NHWC [8][HW][64]
    float* __restrict__ w81)        // [4][HW][81]
{
    int n = blockIdx.y;
    int warp = threadIdx.x >> 5, l = threadIdx.x & 31;
    int p = blockIdx.x * 8 + warp;
    if (p >= HW) return;
    int y = p / WB, x = p - y * WB;

    const float* esel = e2 + ((size_t)n * HW + p) * CE;
    const float* ecur = e2 + (size_t)(n + BQ) * HW * CE;
    float2 es = *(const float2*)(esel + 2 * l);

    float c0 = 0.f, c1 = 0.f, c2 = -3.0e38f;
    int k = 0;
#pragma unroll
    for (int di = -RR; di <= RR; di++) {
        int yy = y + di; bool vy = (unsigned)yy < HB;
#pragma unroll
        for (int dj = -RR; dj <= RR; dj++) {
            int xx = x + dj;
            float2 ec = make_float2(0.f, 0.f);
            if (vy && (unsigned)xx < WB)
                ec = *(const float2*)(ecur + ((size_t)(yy * WB + xx)) * CE + 2 * l);
            float ps = es.x * ec.x + es.y * ec.y;
#pragma unroll
            for (int s = 16; s > 0; s >>= 1) ps += __shfl_xor_sync(0xffffffffu, ps, s);
            if (k < 32)      { if (l == k)      c0 = ps; }
            else if (k < 64) { if (l == k - 32) c1 = ps; }
            else             { if (l == k - 64) c2 = ps; }
            k++;
        }
    }
    // warp softmax over 81 logits (3 per lane; c2 valid only for l<17)
    float mx = fmaxf(c0, fmaxf(c1, c2));
#pragma unroll
    for (int s = 16; s > 0; s >>= 1) mx = fmaxf(mx, __shfl_xor_sync(0xffffffffu, mx, s));
    float e0 = __expf(c0 - mx);
    float e1 = __expf(c1 - mx);
    float e2v = (l < 17) ? __expf(c2 - mx) : 0.f;
    float sm = e0 + e1 + e2v;
#pragma unroll
    for (int s = 16; s > 0; s >>= 1) sm += __shfl_xor_sync(0xffffffffu, sm, s);
    float inv = 1.f / sm;
    size_t base = ((size_t)n * HW + p) * K81;
    w81[base + l]      = e0 * inv;
    w81[base + 32 + l] = e1 * inv;
    if (l < 17) w81[base + 64 + l] = e2v * inv;
}

// ---------------- weighted neighborhood aggregation --------------------------
// warp per pixel; lanes over 32 channel-quads of NHWC feature_select.
__global__ __launch_bounds__(256) void k_align(
    const float* __restrict__ w81,  // [4][HW][81]
    const float* __restrict__ fsn,  // NHWC [4][HW][128]
    float* __restrict__ aln)        // NHWC [4][HW][128]
{
    int n = blockIdx.y;
    int warp = threadIdx.x >> 5, l = threadIdx.x & 31;
    int p = blockIdx.x * 8 + warp;
    if (p >= HW) return;
    int y = p / WB, x = p - y * WB;

    const float* wp = w81 + ((size_t)n * HW + p) * K81;
    const float* fb = fsn + (size_t)n * HW * CI;
    float4 acc = make_float4(0.f, 0.f, 0.f, 0.f);
    int k = 0;
#pragma unroll
    for (int di = -RR; di <= RR; di++) {
        int yy = y + di; bool vy = (unsigned)yy < HB;
#pragma unroll
        for (int dj = -RR; dj <= RR; dj++) {
            int xx = x + dj;
            if (vy && (unsigned)xx < WB) {
                float wv = wp[k];
                float4 f = *(const float4*)(fb + ((size_t)(yy * WB + xx)) * CI + 4 * l);
                acc.x += wv * f.x; acc.y += wv * f.y;
                acc.z += wv * f.z; acc.w += wv * f.w;
            }
            k++;
        }
    }
    *(float4*)(aln + ((size_t)n * HW + p) * CI + 4 * l) = acc;
}

// ---------------- ag3: 1x1 conv 32->1 + ReLU ---------------------------------
__global__ void k_ag3(const float* __restrict__ a2, const float* __restrict__ w,
                      const float* __restrict__ bias, float* __restrict__ a3) {
    int n = blockIdx.y;
    int p = blockIdx.x * 256 + threadIdx.x;
    if (p >= HW) return;
    const float* src = a2 + (size_t)n * 32 * HW;
    float s = bias[0];
#pragma unroll
    for (int ic = 0; ic < 32; ic++) s += w[ic] * src[(size_t)ic * HW + p];
    a3[(size_t)n * HW + p] = fmaxf(s, 0.f);
}

// ---------------- final 2-way softmax blend ----------------------------------
__global__ void k_final(const float* __restrict__ a3, const float* __restrict__ alc,
                        const float* __restrict__ fc, float* __restrict__ out) {
    size_t idx = (size_t)blockIdx.x * 256 + threadIdx.x;
    if (idx >= (size_t)BQ * CI * HW) return;
    int p = (int)(idx % HW);
    int nc = (int)(idx / HW);
    int n = nc / CI;
    float as = a3[(size_t)n * HW + p];
    float ac = a3[(size_t)(n + BQ) * HW + p];
    float m = fmaxf(as, ac);
    float ea = __expf(as - m), eb = __expf(ac - m);
    float inv = 1.f / (ea + eb);
    out[idx] = (ea * inv) * alc[idx] + (eb * inv) * fc[idx];
}

// ---------------- launch ------------------------------------------------------
extern "C" void kernel_launch(void* const* d_in, const int* in_sizes, int n_in,
                              void* d_out, int out_size) {
    const float* fs    = (const float*)d_in[0];
    const float* fc    = (const float*)d_in[1];
    const float* ec1_w = (const float*)d_in[2];
    const float* ec1_b = (const float*)d_in[3];
    const float* ec2_w = (const float*)d_in[4];
    const float* ec2_b = (const float*)d_in[5];
    const float* ag1_w = (const float*)d_in[6];
    const float* ag1_b = (const float*)d_in[7];
    const float* ag2_w = (const float*)d_in[8];
    const float* ag2_b = (const float*)d_in[9];
    const float* ag3_w = (const float*)d_in[10];
    const float* ag3_b = (const float*)d_in[11];
    float* out = (float*)d_out;

    float *t1, *e2, *w81, *fsn, *aln, *alc, *a1, *a2, *a3;
    cudaGetSymbolAddress((void**)&t1,  g_T1);
    cudaGetSymbolAddress((void**)&e2,  g_E2);
    cudaGetSymbolAddress((void**)&w81, g_W81);
    cudaGetSymbolAddress((void**)&fsn, g_FSN);
    cudaGetSymbolAddress((void**)&aln, g_ALN);
    cudaGetSymbolAddress((void**)&alc, g_ALC);
    cudaGetSymbolAddress((void**)&a1,  g_A1);
    cudaGetSymbolAddress((void**)&a2,  g_A2);
    cudaGetSymbolAddress((void**)&a3,  g_A3);

    const int PBLK = (HW + 255) / 256;  // 157

    // feature_select NCHW -> NHWC (for align gather)
    k_trans<<<dim3(HW / 32, CI / 32, BQ), dim3(32, 8)>>>(fs, fsn, CI, HW);
    // encoder
    k_conv1<CI><<<dim3(PBLK, NBT), 256>>>(fs, fc, ec1_w, ec1_b, t1);
    k_conv3<CE, true><<<dim3(PBLK, NBT), 256>>>(t1, ec2_w, ec2_b, e2);
    // correlation + softmax
    k_corr<<<dim3(HW / 8, BQ), 256>>>(e2, w81);
    // weighted aggregation
    k_align<<<dim3(HW / 8, BQ), 256>>>(w81, fsn, aln);
    k_trans<<<dim3(CI / 32, HW / 32, BQ), dim3(32, 8)>>>(aln, alc, HW, CI);
    // gating head
    k_conv1<CI><<<dim3(PBLK, NBT), 256>>>(alc, fc, ag1_w, ag1_b, a1);
    k_conv3<32, false><<<dim3(PBLK, NBT), 256>>>(a1, ag2_w, ag2_b, a2);
    k_ag3<<<dim3(PBLK, NBT), 256>>>(a2, ag3_w, ag3_b, a3);
    // final blend
    size_t tot = (size_t)BQ * CI * HW;
    k_final<<<(unsigned)((tot + 255) / 256), 256>>>(a3, alc, fc, out);
}

// round 3
// speedup vs baseline: 1.5315x; 1.5315x over previous
#include <cuda_runtime.h>
#include <cuda_bf16.h>
#include <cstdint>

// Problem constants
#define HB 200
#define WB 200
#define HW 40000          // H*W
#define BQ 4              // batch
#define NBT 8             // 2*batch (cat)
#define CI 128            // input channels
#define CE 64             // embed channels
#define RR 4              // neighborhood radius
#define K81 81            // 9x9 offsets

typedef unsigned long long ull;

// ---------------- packed f32x2 helpers ----------------
__device__ __forceinline__ ull pack2(float x, float y) {
    ull r; asm("mov.b64 %0,{%1,%2};" : "=l"(r) : "f"(x), "f"(y)); return r;
}
__device__ __forceinline__ float2 unpack2(ull v) {
    float2 r; asm("mov.b64 {%0,%1},%2;" : "=f"(r.x), "=f"(r.y) : "l"(v)); return r;
}
__device__ __forceinline__ void ffma2(ull& c, ull a, ull b) {
    asm("fma.rn.f32x2 %0,%1,%2,%0;" : "+l"(c) : "l"(a), "l"(b));
}

__device__ __forceinline__ uint32_t smem_u32(const void* p) {
    uint32_t a;
    asm("{ .reg .u64 t; cvta.to.shared.u64 t, %1; cvt.u32.u64 %0, t; }" : "=r"(a) : "l"(p));
    return a;
}

// warp-level bf16 MMA: D(16x8,f32) += A(16x16,bf16) * B(16x8,bf16)
__device__ __forceinline__ void mma16816(float* c, const uint32_t* a, uint32_t b0, uint32_t b1) {
    asm volatile(
        "mma.sync.aligned.m16n8k16.row.col.f32.bf16.bf16.f32 "
        "{%0,%1,%2,%3}, {%4,%5,%6,%7}, {%8,%9}, {%0,%1,%2,%3};"
        : "+f"(c[0]), "+f"(c[1]), "+f"(c[2]), "+f"(c[3])
        : "r"(a[0]), "r"(a[1]), "r"(a[2]), "r"(a[3]), "r"(b0), "r"(b1));
}
__device__ __forceinline__ void ldmatrix_x4(uint32_t* r, uint32_t addr) {
    asm volatile("ldmatrix.sync.aligned.m8n8.x4.shared.b16 {%0,%1,%2,%3}, [%4];"
                 : "=r"(r[0]), "=r"(r[1]), "=r"(r[2]), "=r"(r[3]) : "r"(addr));
}

// ---------------- scratch (device globals) ------------
__device__ float g_T1 [(size_t)NBT * CE * HW];           // ec1/ag1 out, NCHW fp32
__device__ __nv_bfloat16 g_T1B[(size_t)NBT * HW * CE];   // NHWC bf16 version
__device__ float g_E2 [(size_t)NBT * HW * CE];           // ec2 out, NHWC fp32
__device__ float g_W81[(size_t)BQ  * HW * K81];
__device__ float g_FSN[(size_t)BQ  * HW * CI];
__device__ float g_ALN[(size_t)BQ  * HW * CI];
__device__ float g_ALC[(size_t)BQ  * CI * HW];
__device__ float g_A2 [(size_t)NBT * HW * 32];           // ag2 out, NHWC fp32
__device__ float g_A3 [(size_t)NBT * HW];
__device__ __nv_bfloat16 g_WTE[9 * 64 * 64];             // ec2 weights bf16 [tap][oc][ic]
__device__ __nv_bfloat16 g_WTA[9 * 32 * 64];             // ag2 weights bf16

// ---------------- generic 32x32 tiled transpose: [n][A][B] -> [n][B][A] ------
__global__ void k_trans(const float* __restrict__ src, float* __restrict__ dst,
                        int A, int B) {
    __shared__ float t[32][33];
    int n = blockIdx.z;
    size_t base = (size_t)n * A * B;
    int a0 = blockIdx.y * 32, b0 = blockIdx.x * 32;
    int tx = threadIdx.x, ty = threadIdx.y;
#pragma unroll
    for (int i = 0; i < 4; i++) {
        int a = a0 + ty + i * 8, b = b0 + tx;
        if (a < A && b < B) t[ty + i * 8][tx] = src[base + (size_t)a * B + b];
    }
    __syncthreads();
#pragma unroll
    for (int i = 0; i < 4; i++) {
        int b = b0 + ty + i * 8, a = a0 + tx;
        if (a < A && b < B) dst[base + (size_t)b * A + a] = t[tx][ty + i * 8];
    }
}

// ---------------- NCHW fp32 [n][64][HW] -> NHWC bf16 [n][HW][64] --------------
__global__ void k_tobf16(const float* __restrict__ src, __nv_bfloat16* __restrict__ dst) {
    __shared__ float t[32][33];
    int n = blockIdx.z, at = blockIdx.y;
    const float* s = src + (size_t)n * CE * HW;
    __nv_bfloat16* d = dst + (size_t)n * HW * CE;
    int b0 = blockIdx.x * 32;
    int tx = threadIdx.x, ty = threadIdx.y;
#pragma unroll
    for (int i = 0; i < 4; i++)
        t[ty + i * 8][tx] = s[(size_t)(at * 32 + ty + i * 8) * HW + b0 + tx];
    __syncthreads();
#pragma unroll
    for (int i = 0; i < 4; i++)
        d[(size_t)(b0 + ty + i * 8) * CE + at * 32 + tx] = __float2bfloat16(t[tx][ty + i * 8]);
}

// ---------------- weight prep: [OC][64][3][3] fp32 -> [9][OC][64] bf16 --------
__global__ void k_wprep(const float* __restrict__ w, __nv_bfloat16* __restrict__ dst, int OC) {
    int i = blockIdx.x * 256 + threadIdx.x;
    int tot = 9 * OC * 64;
    if (i >= tot) return;
    int ic = i & 63;
    int rest = i >> 6;
    int oc = rest % OC;
    int tap = rest / OC;
    dst[((size_t)tap * OC + oc) * 64 + ic] = __float2bfloat16(w[((size_t)oc * 64 + ic) * 9 + tap]);
}

// ---------------- 1x1 conv + ReLU:  NCHW in -> NCHW out (OC=64) --------------
template <int IC>
__global__ __launch_bounds__(256) void k_conv1(
    const float* __restrict__ in0, const float* __restrict__ in1,
    const float* __restrict__ w, const float* __restrict__ bias,
    float* __restrict__ out)
{
    __shared__ __align__(16) float ws[IC][64];
    int n = blockIdx.y;
    const float* src = ((n < BQ) ? in0 : in1) + (size_t)(n & 3) * IC * HW;
    int tid = threadIdx.x;
    for (int i = tid; i < IC * 64; i += 256) {
        int ic = i >> 6, oc = i & 63;
        ws[ic][oc] = w[oc * IC + ic];
    }
    __syncthreads();

    int ocg = tid >> 6, j = tid & 63;
    int pb = blockIdx.x * 256;
    int p[4]; bool pv[4];
#pragma unroll
    for (int m = 0; m < 4; m++) { p[m] = pb + j + 64 * m; pv[m] = p[m] < HW; }

    ull acc[4][8];
#pragma unroll
    for (int m = 0; m < 4; m++)
#pragma unroll
        for (int u = 0; u < 8; u++) acc[m][u] = 0ull;

    for (int ic = 0; ic < IC; ic++) {
        ull x2[4];
#pragma unroll
        for (int m = 0; m < 4; m++) {
            float xv = pv[m] ? src[(size_t)ic * HW + p[m]] : 0.f;
            x2[m] = pack2(xv, xv);
        }
        const ull* wr = reinterpret_cast<const ull*>(&ws[ic][ocg * 16]);
        ull wv[8];
#pragma unroll
        for (int u = 0; u < 8; u++) wv[u] = wr[u];
#pragma unroll
        for (int m = 0; m < 4; m++)
#pragma unroll
            for (int u = 0; u < 8; u++) ffma2(acc[m][u], wv[u], x2[m]);
    }

    float* op = out + (size_t)n * 64 * HW;
#pragma unroll
    for (int m = 0; m < 4; m++) {
        if (!pv[m]) continue;
#pragma unroll
        for (int u = 0; u < 8; u++) {
            float2 v = unpack2(acc[m][u]);
            int oc = ocg * 16 + 2 * u;
            op[(size_t)oc * HW + p[m]]       = fmaxf(v.x + bias[oc], 0.f);
            op[(size_t)(oc + 1) * HW + p[m]] = fmaxf(v.y + bias[oc + 1], 0.f);
        }
    }
}

// ---------------- 3x3 conv via warp-level bf16 mma.sync -----------------------
// CTA: 128 pixels (M) x OC (N). K = 9 taps x 64 ic. A tile rebuilt per tap.
// Input NHWC bf16 [8][HW][64]; weights [9][OC][64] bf16; output NHWC fp32.
// SMEM rows padded to 72 halves (144B) for conflict-free ldmatrix / LDS.
template <int OC>
__global__ __launch_bounds__(256) void conv3_hmma(
    const __nv_bfloat16* __restrict__ inb,
    const __nv_bfloat16* __restrict__ wt,
    const float* __restrict__ bias,
    float* __restrict__ out)
{
    constexpr int LDA = 72;               // halves per A row
    constexpr int NT  = OC / 8;           // n-tiles per warp
    __shared__ __align__(16) __nv_bfloat16 As[128 * LDA];
    __shared__ __align__(16) __nv_bfloat16 Bs[OC * LDA];

    int tid = threadIdx.x;
    int wid = tid >> 5, l = tid & 31;
    int n = blockIdx.y;
    int p0 = blockIdx.x * 128;

    // A rebuild mapping: thread t handles row r=t>>1, half h=t&1 (32 halves)
    int ar = tid >> 1, ah = tid & 1;
    int ap = p0 + ar;
    bool apv = ap < HW;
    int ay = ap / WB, ax = ap - ay * WB;

    uint32_t as_base = smem_u32(As);
    uint32_t bs_base = smem_u32(Bs);

    float acc[NT][4];
#pragma unroll
    for (int t = 0; t < NT; t++)
#pragma unroll
        for (int i = 0; i < 4; i++) acc[t][i] = 0.f;

    // ldmatrix lane address for this warp (A row-major, m16k16 tiles)
    int m0 = wid * 16;

    for (int tap = 0; tap < 9; tap++) {
        int dy = tap / 3 - 1, dx = tap % 3 - 1;
        __syncthreads();
        // --- rebuild A tile
        {
            bool v = apv && ((unsigned)(ay + dy) < HB) && ((unsigned)(ax + dx) < WB);
            const uint4* src = reinterpret_cast<const uint4*>(
                inb + ((size_t)n * HW + (ap + dy * WB + dx)) * CE + ah * 32);
            uint4* dst = reinterpret_cast<uint4*>(As + ar * LDA + ah * 32);
            uint4 zz = make_uint4(0u, 0u, 0u, 0u);
#pragma unroll
            for (int c = 0; c < 4; c++) dst[c] = v ? src[c] : zz;
        }
        // --- stage B tap: OC rows x 64 halves
        if (tid < OC * 2) {
            int row = tid >> 1, h = tid & 1;
            const uint4* src = reinterpret_cast<const uint4*>(
                wt + ((size_t)tap * OC + row) * 64 + h * 32);
            uint4* dst = reinterpret_cast<uint4*>(Bs + row * LDA + h * 32);
#pragma unroll
            for (int c = 0; c < 4; c++) dst[c] = src[c];
        }
        __syncthreads();

        // --- 4 K-chunks of 16
#pragma unroll
        for (int ks = 0; ks < 4; ks++) {
            uint32_t afrag[4];
            uint32_t aaddr = as_base +
                ((m0 + (l & 15)) * LDA + ((l >> 4) * 8 + ks * 16)) * 2;
            ldmatrix_x4(afrag, aaddr);
#pragma unroll
            for (int nt = 0; nt < NT; nt++) {
                uint32_t baddr = bs_base +
                    ((nt * 8 + (l >> 2)) * LDA + (ks * 16 + (l & 3) * 2)) * 2;
                uint32_t b0 = *reinterpret_cast<const uint32_t*>((const char*)nullptr + 0); // placeholder (unused)
                (void)b0;
                uint32_t bv0, bv1;
                asm volatile("ld.shared.b32 %0, [%1];" : "=r"(bv0) : "r"(baddr));
                asm volatile("ld.shared.b32 %0, [%1];" : "=r"(bv1) : "r"(baddr + 16));
                mma16816(acc[nt], afrag, bv0, bv1);
            }
        }
    }

    // --- epilogue: bias + ReLU, NHWC fp32 stores
    int row_a = m0 + (l >> 2);       // C rows t/4 and t/4+8
    int col0 = (l & 3) * 2;
#pragma unroll
    for (int half = 0; half < 2; half++) {
        int prow = p0 + row_a + half * 8;
        if (prow >= HW) continue;
        float* ob = out + ((size_t)n * HW + prow) * OC;
#pragma unroll
        for (int nt = 0; nt < NT; nt++) {
            int c = nt * 8 + col0;
            float2 v;
            v.x = fmaxf(acc[nt][half * 2 + 0] + bias[c],     0.f);
            v.y = fmaxf(acc[nt][half * 2 + 1] + bias[c + 1], 0.f);
            *reinterpret_cast<float2*>(ob + c) = v;
        }
    }
}

// ---------------- correlation (81 offsets) + softmax, fused ------------------
__global__ __launch_bounds__(256) void k_corr(
    const float* __restrict__ e2, float* __restrict__ w81)
{
    int n = blockIdx.y;
    int warp = threadIdx.x >> 5, l = threadIdx.x & 31;
    int p = blockIdx.x * 8 + warp;
    if (p >= HW) return;
    int y = p / WB, x = p - y * WB;

    const float* esel = e2 + ((size_t)n * HW + p) * CE;
    const float* ecur = e2 + (size_t)(n + BQ) * HW * CE;
    float2 es = *(const float2*)(esel + 2 * l);

    float c0 = 0.f, c1 = 0.f, c2 = -3.0e38f;
    int k = 0;
#pragma unroll
    for (int di = -RR; di <= RR; di++) {
        int yy = y + di; bool vy = (unsigned)yy < HB;
#pragma unroll
        for (int dj = -RR; dj <= RR; dj++) {
            int xx = x + dj;
            float2 ec = make_float2(0.f, 0.f);
            if (vy && (unsigned)xx < WB)
                ec = *(const float2*)(ecur + ((size_t)(yy * WB + xx)) * CE + 2 * l);
            float ps = es.x * ec.x + es.y * ec.y;
#pragma unroll
            for (int s = 16; s > 0; s >>= 1) ps += __shfl_xor_sync(0xffffffffu, ps, s);
            if (k < 32)      { if (l == k)      c0 = ps; }
            else if (k < 64) { if (l == k - 32) c1 = ps; }
            else             { if (l == k - 64) c2 = ps; }
            k++;
        }
    }
    float mx = fmaxf(c0, fmaxf(c1, c2));
#pragma unroll
    for (int s = 16; s > 0; s >>= 1) mx = fmaxf(mx, __shfl_xor_sync(0xffffffffu, mx, s));
    float e0 = __expf(c0 - mx);
    float e1 = __expf(c1 - mx);
    float e2v = (l < 17) ? __expf(c2 - mx) : 0.f;
    float sm = e0 + e1 + e2v;
#pragma unroll
    for (int s = 16; s > 0; s >>= 1) sm += __shfl_xor_sync(0xffffffffu, sm, s);
    float inv = 1.f / sm;
    size_t base = ((size_t)n * HW + p) * K81;
    w81[base + l]      = e0 * inv;
    w81[base + 32 + l] = e1 * inv;
    if (l < 17) w81[base + 64 + l] = e2v * inv;
}

// ---------------- weighted neighborhood aggregation --------------------------
__global__ __launch_bounds__(256) void k_align(
    const float* __restrict__ w81, const float* __restrict__ fsn,
    float* __restrict__ aln)
{
    int n = blockIdx.y;
    int warp = threadIdx.x >> 5, l = threadIdx.x & 31;
    int p = blockIdx.x * 8 + warp;
    if (p >= HW) return;
    int y = p / WB, x = p - y * WB;

    const float* wp = w81 + ((size_t)n * HW + p) * K81;
    const float* fb = fsn + (size_t)n * HW * CI;
    float4 acc = make_float4(0.f, 0.f, 0.f, 0.f);
    int k = 0;
#pragma unroll
    for (int di = -RR; di <= RR; di++) {
        int yy = y + di; bool vy = (unsigned)yy < HB;
#pragma unroll
        for (int dj = -RR; dj <= RR; dj++) {
            int xx = x + dj;
            if (vy && (unsigned)xx < WB) {
                float wv = wp[k];
                float4 f = *(const float4*)(fb + ((size_t)(yy * WB + xx)) * CI + 4 * l);
                acc.x += wv * f.x; acc.y += wv * f.y;
                acc.z += wv * f.z; acc.w += wv * f.w;
            }
            k++;
        }
    }
    *(float4*)(aln + ((size_t)n * HW + p) * CI + 4 * l) = acc;
}

// ---------------- ag3: 1x1 conv 32->1 + ReLU (NHWC input) --------------------
__global__ void k_ag3(const float* __restrict__ a2, const float* __restrict__ w,
                      const float* __restrict__ bias, float* __restrict__ a3) {
    int n = blockIdx.y;
    int p = blockIdx.x * 256 + threadIdx.x;
    if (p >= HW) return;
    const float* src = a2 + ((size_t)n * HW + p) * 32;
    float s = bias[0];
#pragma unroll
    for (int c = 0; c < 32; c += 4) {
        float4 f = *(const float4*)(src + c);
        s += w[c] * f.x + w[c + 1] * f.y + w[c + 2] * f.z + w[c + 3] * f.w;
    }
    a3[(size_t)n * HW + p] = fmaxf(s, 0.f);
}

// ---------------- final 2-way softmax blend ----------------------------------
__global__ void k_final(const float* __restrict__ a3, const float* __restrict__ alc,
                        const float* __restrict__ fc, float* __restrict__ out) {
    size_t idx = (size_t)blockIdx.x * 256 + threadIdx.x;
    if (idx >= (size_t)BQ * CI * HW) return;
    int p = (int)(idx % HW);
    int nc = (int)(idx / HW);
    int n = nc / CI;
    float as = a3[(size_t)n * HW + p];
    float ac = a3[(size_t)(n + BQ) * HW + p];
    float m = fmaxf(as, ac);
    float ea = __expf(as - m), eb = __expf(ac - m);
    float inv = 1.f / (ea + eb);
    out[idx] = (ea * inv) * alc[idx] + (eb * inv) * fc[idx];
}

// ---------------- launch ------------------------------------------------------
extern "C" void kernel_launch(void* const* d_in, const int* in_sizes, int n_in,
                              void* d_out, int out_size) {
    const float* fs    = (const float*)d_in[0];
    const float* fc    = (const float*)d_in[1];
    const float* ec1_w = (const float*)d_in[2];
    const float* ec1_b = (const float*)d_in[3];
    const float* ec2_w = (const float*)d_in[4];
    const float* ec2_b = (const float*)d_in[5];
    const float* ag1_w = (const float*)d_in[6];
    const float* ag1_b = (const float*)d_in[7];
    const float* ag2_w = (const float*)d_in[8];
    const float* ag2_b = (const float*)d_in[9];
    const float* ag3_w = (const float*)d_in[10];
    const float* ag3_b = (const float*)d_in[11];
    float* out = (float*)d_out;

    float *t1, *e2, *w81, *fsn, *aln, *alc, *a2, *a3;
    __nv_bfloat16 *t1b, *wte, *wta;
    cudaGetSymbolAddress((void**)&t1,  g_T1);
    cudaGetSymbolAddress((void**)&t1b, g_T1B);
    cudaGetSymbolAddress((void**)&e2,  g_E2);
    cudaGetSymbolAddress((void**)&w81, g_W81);
    cudaGetSymbolAddress((void**)&fsn, g_FSN);
    cudaGetSymbolAddress((void**)&aln, g_ALN);
    cudaGetSymbolAddress((void**)&alc, g_ALC);
    cudaGetSymbolAddress((void**)&a2,  g_A2);
    cudaGetSymbolAddress((void**)&a3,  g_A3);
    cudaGetSymbolAddress((void**)&wte, g_WTE);
    cudaGetSymbolAddress((void**)&wta, g_WTA);

    const int PBLK = (HW + 255) / 256;   // 157
    const int MBLK = (HW + 127) / 128;   // 313

    // weight prep (independent, cheap)
    k_wprep<<<(9 * 64 * 64 + 255) / 256, 256>>>(ec2_w, wte, 64);
    k_wprep<<<(9 * 32 * 64 + 255) / 256, 256>>>(ag2_w, wta, 32);

    // feature_select NCHW -> NHWC (for align gather)
    k_trans<<<dim3(HW / 32, CI / 32, BQ), dim3(32, 8)>>>(fs, fsn, CI, HW);

    // encoder
    k_conv1<CI><<<dim3(PBLK, NBT), 256>>>(fs, fc, ec1_w, ec1_b, t1);
    k_tobf16<<<dim3(HW / 32, 2, NBT), dim3(32, 8)>>>(t1, t1b);
    conv3_hmma<64><<<dim3(MBLK, NBT), 256>>>(t1b, wte, ec2_b, e2);

    // correlation + softmax
    k_corr<<<dim3(HW / 8, BQ), 256>>>(e2, w81);

    // weighted aggregation
    k_align<<<dim3(HW / 8, BQ), 256>>>(w81, fsn, aln);
    k_trans<<<dim3(CI / 32, HW / 32, BQ), dim3(32, 8)>>>(aln, alc, HW, CI);

    // gating head
    k_conv1<CI><<<dim3(PBLK, NBT), 256>>>(alc, fc, ag1_w, ag1_b, t1);
    k_tobf16<<<dim3(HW / 32, 2, NBT), dim3(32, 8)>>>(t1, t1b);
    conv3_hmma<32><<<dim3(MBLK, NBT), 256>>>(t1b, wta, ag2_b, a2);
    k_ag3<<<dim3(PBLK, NBT), 256>>>(a2, ag3_w, ag3_b, a3);

    // final blend
    size_t tot = (size_t)BQ * CI * HW;
    k_final<<<(unsigned)((tot + 255) / 256), 256>>>(a3, alc, fc, out);
}